// round 13
// baseline (speedup 1.0000x reference)
#include <cuda_runtime.h>
#include <cuda_fp16.h>
#include <cstdint>

// Problem dims
#define BATCH 8192
#define IN    1024
#define OUT   1024

// GEMM tiling: block 64x128, 4 warps (2M x 2N), warp tile 32x64, fp16 math,
// A converted fp32->fp16 in-kernel (LDG -> cvt -> STS).
#define BM 64
#define BN 128
#define BKH 64            // K-elements per stage (= 128 B fp16 per row)
#define KT (IN / BKH)     // 16 k-iterations
#define STAGES 3
#define THREADS 128

#define A_STAGE_HALVES (BM * BKH)           // 4096 halves = 8 KB
#define B_STAGE_HALVES (BN * BKH)           // 8192 halves = 16 KB
#define A_STAGE_BYTES (A_STAGE_HALVES * 2)
#define B_STAGE_BYTES (B_STAGE_HALVES * 2)

// Scratch: fp16 effective weights only (x is converted inside the GEMM)
__device__ __half g_weffh[OUT * IN];   // [O, I], K-contiguous

// ---------------------------------------------------------------------------
// Helpers
// ---------------------------------------------------------------------------
__device__ __forceinline__ uint32_t h2_bits(__half2 h) {
    return *reinterpret_cast<uint32_t*>(&h);
}
__device__ __forceinline__ void cp_async16(void* s, const void* g) {
    uint32_t sa = (uint32_t)__cvta_generic_to_shared(s);
    asm volatile("cp.async.cg.shared.global [%0], [%1], 16;\n" :: "r"(sa), "l"(g));
}
__device__ __forceinline__ void cp_commit() {
    asm volatile("cp.async.commit_group;\n");
}
__device__ __forceinline__ void cp_wait1() {
    asm volatile("cp.async.wait_group 1;\n");
}
__device__ __forceinline__ void ldsm_x4(uint32_t* r, uint32_t saddr) {
    asm volatile("ldmatrix.sync.aligned.m8n8.x4.shared.b16 {%0,%1,%2,%3}, [%4];"
        : "=r"(r[0]), "=r"(r[1]), "=r"(r[2]), "=r"(r[3]) : "r"(saddr));
}
__device__ __forceinline__ void sts128(uint32_t addr, uint32_t r0, uint32_t r1,
                                       uint32_t r2, uint32_t r3) {
    asm volatile("st.shared.v4.b32 [%0], {%1,%2,%3,%4};"
                 :: "r"(addr), "r"(r0), "r"(r1), "r"(r2), "r"(r3) : "memory");
}
// fp16 MMA, fp32 accumulate: D[16x8] += A[16x16] * B[16x8]
__device__ __forceinline__ void mma_f16(float* c, const uint32_t* a, const uint32_t* b) {
    asm volatile(
        "mma.sync.aligned.m16n8k16.row.col.f32.f16.f16.f32 "
        "{%0,%1,%2,%3},{%4,%5,%6,%7},{%8,%9},{%0,%1,%2,%3};\n"
        : "+f"(c[0]), "+f"(c[1]), "+f"(c[2]), "+f"(c[3])
        : "r"(a[0]), "r"(a[1]), "r"(a[2]), "r"(a[3]), "r"(b[0]), "r"(b[1]));
}

// ---------------------------------------------------------------------------
// Kernel A (prep): build+round w_eff -> g_weffh (fp16-rn). x untouched.
// ---------------------------------------------------------------------------
__global__ void prep_kernel(const float4* __restrict__ coef,
                            const float* __restrict__ w) {
    int i = (blockIdx.x * blockDim.x + threadIdx.x) * 2;   // 2 elements/thread
    float r0, r1;
    {
        float4 c0 = coef[2 * i];
        float4 c1 = coef[2 * i + 1];
        float s = ((c0.x + c0.y) + (c0.z + c0.w)) + ((c1.x + c1.y) + (c1.z + c1.w));
        r0 = s * w[i];
    }
    {
        float4 c0 = coef[2 * (i + 1)];
        float4 c1 = coef[2 * (i + 1) + 1];
        float s = ((c0.x + c0.y) + (c0.z + c0.w)) + ((c1.x + c1.y) + (c1.z + c1.w));
        r1 = s * w[i + 1];
    }
    reinterpret_cast<uint32_t*>(g_weffh)[i / 2] = h2_bits(__floats2half2_rn(r0, r1));
}

// ---------------------------------------------------------------------------
// Kernel B: C[8192,1024] = fp16(X) @ Weffh^T
//   A path: LDG fp32 -> cvt fp16 -> swizzled STS (pipelined 1 iter ahead)
//   B path: cp.async fp16 (3-stage groups)
// ---------------------------------------------------------------------------
__global__ void __launch_bounds__(THREADS, 3)
gemm_f16(const float* __restrict__ X, float* __restrict__ C) {
    extern __shared__ __half smem[];
    __half* Bs = smem + STAGES * A_STAGE_HALVES;

    const int tid    = threadIdx.x;
    const int warpId = tid >> 5;              // 0..3
    const int lane   = tid & 31;
    const int g      = lane >> 2;   // 0..7
    const int t4     = lane & 3;    // 0..3
    const int warpM  = warpId & 1;  // 2 warps in M (32 rows each)
    const int warpN  = warpId >> 1; // 2 warps in N (64 cols each)

    const int bm = blockIdx.y * BM;
    const int bn = blockIdx.x * BN;

    // B-tile loader lanes
    const int lr = tid >> 3;   // 0..15
    const int lc = tid & 7;    // 0..7
    const __half* Bg = g_weffh + (size_t)bn * IN;

    // A-staging lanes: 2 threads per row, 32 floats each
    const int arow  = tid >> 1;    // 0..63
    const int ahalf = tid & 1;     // 0..1
    const float* Axg = X + (size_t)(bm + arow) * IN + ahalf * 32;

    const uint32_t smem_base = (uint32_t)__cvta_generic_to_shared(smem);
    const uint32_t b_region  = smem_base + STAGES * A_STAGE_BYTES;
    const uint32_t a_sts_row = smem_base + arow * 128;   // + stage ofs + group

    // ldmatrix per-lane byte offsets (within a stage)
    const int j8 = lane >> 3;
    const int rw = lane & 7;
    uint32_t a_off[2], b_off[4];
#pragma unroll
    for (int mi = 0; mi < 2; mi++) {
        int row = warpM * 32 + mi * 16 + (j8 & 1) * 8 + rw;
        int c   = j8 >> 1;
        a_off[mi] = row * 128 + ((c ^ (row & 7)) * 16);
    }
#pragma unroll
    for (int nj = 0; nj < 4; nj++) {
        int n = warpN * 64 + nj * 16 + (j8 >> 1) * 8 + rw;
        int c = j8 & 1;
        b_off[nj] = n * 128 + ((c ^ (n & 7)) * 16);
    }

    // Warp tile 32x64: 2 M-frags x 8 N-frags
    float acc[2][8][4];
#pragma unroll
    for (int mi = 0; mi < 2; mi++)
#pragma unroll
        for (int ni = 0; ni < 8; ni++)
#pragma unroll
            for (int k = 0; k < 4; k++) acc[mi][ni][k] = 0.f;

    // ---- helpers as macros over locals ----
#define LOAD_B(stage, kt2)                                                    \
    do {                                                                      \
        __half* bs_ = Bs + (stage) * B_STAGE_HALVES;                          \
        int ko_ = (kt2) * BKH + lc * 8;                                       \
        _Pragma("unroll")                                                     \
        for (int j = 0; j < 8; j++) {                                         \
            int r_ = lr + j * 16;                                             \
            int sw_ = (lc ^ (r_ & 7)) * 8;                                    \
            cp_async16(bs_ + r_ * BKH + sw_, Bg + (size_t)r_ * IN + ko_);     \
        }                                                                     \
    } while (0)

#define LDG_A(kt2, f4)                                                        \
    do {                                                                      \
        const float4* p_ = (const float4*)(Axg + (kt2) * BKH);                \
        _Pragma("unroll")                                                     \
        for (int j = 0; j < 8; j++) (f4)[j] = __ldg(p_ + j);                  \
    } while (0)

#define STS_A(stage, f4)                                                      \
    do {                                                                      \
        uint32_t c2_[16];                                                     \
        _Pragma("unroll")                                                     \
        for (int j = 0; j < 8; j++) {                                         \
            c2_[2 * j]     = h2_bits(__floats2half2_rn((f4)[j].x, (f4)[j].y));\
            c2_[2 * j + 1] = h2_bits(__floats2half2_rn((f4)[j].z, (f4)[j].w));\
        }                                                                     \
        uint32_t base_ = a_sts_row + (stage) * A_STAGE_BYTES;                 \
        _Pragma("unroll")                                                     \
        for (int cc = 0; cc < 4; cc++) {                                      \
            int gl_ = ahalf * 4 + cc;                                         \
            uint32_t ad_ = base_ + ((gl_ ^ (arow & 7)) * 16);                 \
            sts128(ad_, c2_[4 * cc], c2_[4 * cc + 1], c2_[4 * cc + 2],        \
                   c2_[4 * cc + 3]);                                          \
        }                                                                     \
    } while (0)

    float4 fst[8];   // staged A data (fp32) for stage kt+2

    // Prologue: B stages 0,1 via cp.async; A stages 0,1 via LDG/STS; LDG A2.
    LOAD_B(0, 0);
    cp_commit();
    LOAD_B(1, 1);
    cp_commit();
    LDG_A(0, fst);
    STS_A(0, fst);
    LDG_A(1, fst);
    STS_A(1, fst);
    LDG_A(2, fst);   // for STS at iter 0

    for (int kt = 0; kt < KT; kt++) {
        cp_wait1();            // B stage kt resident (kt+1 in flight)
        __syncthreads();       // stage (kt+2)%3 fully consumed; A STS visible

        if (kt + 2 < KT) {
            int s = (kt + 2) % STAGES;
            STS_A(s, fst);     // A data staged one iteration ago
            LOAD_B(s, kt + 2);
        }
        cp_commit();           // keep group accounting uniform
        if (kt + 3 < KT)
            LDG_A(kt + 3, fst);

        const uint32_t a_base = smem_base + (kt % STAGES) * A_STAGE_BYTES;
        const uint32_t b_base = b_region  + (kt % STAGES) * B_STAGE_BYTES;

#pragma unroll
        for (int s = 0; s < 4; s++) {        // four k16 steps per stage
            const uint32_t sx = (uint32_t)s * 32;
            uint32_t af[2][4];
            uint32_t bf[8][2];
#pragma unroll
            for (int mi = 0; mi < 2; mi++)
                ldsm_x4(af[mi], a_base + (a_off[mi] ^ sx));
#pragma unroll
            for (int nj = 0; nj < 4; nj++) {
                uint32_t r[4];
                ldsm_x4(r, b_base + (b_off[nj] ^ sx));
                bf[2 * nj][0]     = r[0];
                bf[2 * nj][1]     = r[1];
                bf[2 * nj + 1][0] = r[2];
                bf[2 * nj + 1][1] = r[3];
            }
#pragma unroll
            for (int mi = 0; mi < 2; mi++)
#pragma unroll
                for (int ni = 0; ni < 8; ni++)
                    mma_f16(acc[mi][ni], af[mi], bf[ni]);
        }
    }

    // Epilogue: fp32 stores
#pragma unroll
    for (int mi = 0; mi < 2; mi++) {
#pragma unroll
        for (int ni = 0; ni < 8; ni++) {
            int row = bm + warpM * 32 + mi * 16 + g;
            int col = bn + warpN * 64 + ni * 8 + t4 * 2;
            float2 v01 = make_float2(acc[mi][ni][0], acc[mi][ni][1]);
            float2 v23 = make_float2(acc[mi][ni][2], acc[mi][ni][3]);
            *reinterpret_cast<float2*>(C + (size_t)row * OUT + col)       = v01;
            *reinterpret_cast<float2*>(C + (size_t)(row + 8) * OUT + col) = v23;
        }
    }
#undef LOAD_B
#undef LDG_A
#undef STS_A
}

// ---------------------------------------------------------------------------
// Harness entry
// ---------------------------------------------------------------------------
extern "C" void kernel_launch(void* const* d_in, const int* in_sizes, int n_in,
                              void* d_out, int out_size) {
    const float*  x    = (const float*)d_in[0];   // [8192,1024] fp32
    const float4* coef = (const float4*)d_in[1];  // [1024,1024,8] fp32
    const float*  w    = (const float*)d_in[2];   // [1024,1024] fp32
    float* out = (float*)d_out;                   // [8192,1024] fp32
    (void)in_sizes; (void)n_in; (void)out_size;

    // Prep: w_eff only (512K threads, 2 elements each)
    prep_kernel<<<(OUT * IN / 2) / 256, 256>>>(coef, w);

    // fp16 GEMM with fused x conversion, 72 KB smem, occ 3
    static const int smem_bytes = STAGES * (A_STAGE_BYTES + B_STAGE_BYTES); // 73728
    cudaFuncSetAttribute(gemm_f16, cudaFuncAttributeMaxDynamicSharedMemorySize, smem_bytes);

    dim3 grid(OUT / BN, BATCH / BM);  // (8, 128) = 1024 CTAs
    gemm_f16<<<grid, THREADS, smem_bytes>>>(x, out);
}

// round 14
// speedup vs baseline: 1.6490x; 1.6490x over previous
#include <cuda_runtime.h>
#include <cuda_fp16.h>
#include <cstdint>

// Problem dims
#define BATCH 8192
#define IN    1024
#define OUT   1024

// GEMM tiling: block 128x128, 4 warps (2M x 2N), warp tile 64x64, fp16
#define BM 128
#define BN 128
#define BKH 64            // K-halves per stage (= 128 bytes per row)
#define KT (IN / BKH)     // 16 k-iterations
#define STAGES 3
#define THREADS 128

#define A_STAGE_HALVES (BM * BKH)           // 8192 halves = 16 KB
#define B_STAGE_HALVES (BN * BKH)           // 8192 halves = 16 KB
#define A_STAGE_BYTES (A_STAGE_HALVES * 2)
#define B_STAGE_BYTES (B_STAGE_HALVES * 2)

// Scratch: fp16-rounded operands, K-contiguous
__device__ __half g_weffh[OUT * IN];   // [O, I]
__device__ __half g_xrh[BATCH * IN];   // [B, I]

// ---------------------------------------------------------------------------
// Helpers
// ---------------------------------------------------------------------------
__device__ __forceinline__ uint32_t h2_bits(__half2 h) {
    return *reinterpret_cast<uint32_t*>(&h);
}
__device__ __forceinline__ void cp_async16(void* s, const void* g) {
    uint32_t sa = (uint32_t)__cvta_generic_to_shared(s);
    asm volatile("cp.async.cg.shared.global [%0], [%1], 16;\n" :: "r"(sa), "l"(g));
}
__device__ __forceinline__ void cp_commit() {
    asm volatile("cp.async.commit_group;\n");
}
__device__ __forceinline__ void cp_wait1() {
    asm volatile("cp.async.wait_group 1;\n");
}
__device__ __forceinline__ void cp_wait0() {
    asm volatile("cp.async.wait_group 0;\n");
}
__device__ __forceinline__ void ldsm_x4(uint32_t* r, uint32_t saddr) {
    asm volatile("ldmatrix.sync.aligned.m8n8.x4.shared.b16 {%0,%1,%2,%3}, [%4];"
        : "=r"(r[0]), "=r"(r[1]), "=r"(r[2]), "=r"(r[3]) : "r"(saddr));
}
// fp16 MMA, fp32 accumulate: D[16x8] += A[16x16] * B[16x8]
__device__ __forceinline__ void mma_f16(float* c, const uint32_t* a, const uint32_t* b) {
    asm volatile(
        "mma.sync.aligned.m16n8k16.row.col.f32.f16.f16.f32 "
        "{%0,%1,%2,%3},{%4,%5,%6,%7},{%8,%9},{%0,%1,%2,%3};\n"
        : "+f"(c[0]), "+f"(c[1]), "+f"(c[2]), "+f"(c[3])
        : "r"(a[0]), "r"(a[1]), "r"(a[2]), "r"(a[3]), "r"(b[0]), "r"(b[1]));
}

// ---------------------------------------------------------------------------
// Kernel A (prep): round x -> g_xrh (fp16-rn), build+round w_eff -> g_weffh
// ---------------------------------------------------------------------------
__global__ void prep_kernel(const float4* __restrict__ x4,
                            const float4* __restrict__ coef,
                            const float* __restrict__ w) {
    const int NXH = BATCH * IN / 8;          // 1M: each handles 8 floats of x
    int idx = blockIdx.x * blockDim.x + threadIdx.x;
    if (idx < NXH) {
        float4 v0 = x4[2 * idx];
        float4 v1 = x4[2 * idx + 1];
        uint4 out;
        out.x = h2_bits(__floats2half2_rn(v0.x, v0.y));
        out.y = h2_bits(__floats2half2_rn(v0.z, v0.w));
        out.z = h2_bits(__floats2half2_rn(v1.x, v1.y));
        out.w = h2_bits(__floats2half2_rn(v1.z, v1.w));
        reinterpret_cast<uint4*>(g_xrh)[idx] = out;
    } else {
        int i = (idx - NXH) * 2;             // 2 w_eff elements per thread
        float r0, r1;
        {
            float4 c0 = coef[2 * i];
            float4 c1 = coef[2 * i + 1];
            float s = ((c0.x + c0.y) + (c0.z + c0.w)) + ((c1.x + c1.y) + (c1.z + c1.w));
            r0 = s * w[i];
        }
        {
            float4 c0 = coef[2 * (i + 1)];
            float4 c1 = coef[2 * (i + 1) + 1];
            float s = ((c0.x + c0.y) + (c0.z + c0.w)) + ((c1.x + c1.y) + (c1.z + c1.w));
            r1 = s * w[i + 1];
        }
        reinterpret_cast<uint32_t*>(g_weffh)[i / 2] = h2_bits(__floats2half2_rn(r0, r1));
    }
}

// ---------------------------------------------------------------------------
// Kernel B: C[8192,1024] = Xh @ Weffh^T  (TN, fp16 mma.sync + ldmatrix,
//           128x128 tiles, 2x2 warps, 64x64 warp tile, occ 2,
//           register-double-buffered fragments)
// ---------------------------------------------------------------------------
// SMEM rows: 128 bytes (64 halves), 8 x 16B groups, swizzle group^=(row&7).
__device__ __forceinline__ void load_stage(const __half* __restrict__ Ag,
                                           const __half* __restrict__ Bg,
                                           __half* as, __half* bs,
                                           int kt, int lr, int lc) {
    int kofs = kt * BKH + lc * 8;            // half index within row
#pragma unroll
    for (int j = 0; j < 8; j++) {            // 128 rows / 16 per pass
        int r = lr + j * 16;
        int sw = (lc ^ (r & 7)) * 8;
        cp_async16(as + r * BKH + sw, Ag + (size_t)r * IN + kofs);
        cp_async16(bs + r * BKH + sw, Bg + (size_t)r * IN + kofs);
    }
}

__global__ void __launch_bounds__(THREADS, 2)
gemm_f16(const __half* __restrict__ A, float* __restrict__ C) {
    extern __shared__ __half smem[];
    __half* As = smem;                            // STAGES * A_STAGE_HALVES
    __half* Bs = smem + STAGES * A_STAGE_HALVES;  // STAGES * B_STAGE_HALVES

    const int tid    = threadIdx.x;
    const int warpId = tid >> 5;              // 0..3
    const int lane   = tid & 31;
    const int g      = lane >> 2;   // 0..7
    const int t4     = lane & 3;    // 0..3
    const int warpM  = warpId & 1;  // 2 warps in M (64 rows each)
    const int warpN  = warpId >> 1; // 2 warps in N (64 cols each)

    const int bm = blockIdx.y * BM;
    const int bn = blockIdx.x * BN;

    const int lr = tid >> 3;   // 0..15
    const int lc = tid & 7;    // 0..7

    const __half* Ag = A + (size_t)bm * IN;
    const __half* Bg = g_weffh + (size_t)bn * IN;

    // ldmatrix per-lane byte offsets (relative to stage A / stage B base).
    const int j8 = lane >> 3;   // which 8x8 matrix of the x4
    const int rw = lane & 7;    // row within it
    uint32_t a_off[4], b_off[4];
#pragma unroll
    for (int mi = 0; mi < 4; mi++) {
        int row = warpM * 64 + mi * 16 + (j8 & 1) * 8 + rw;
        int c   = j8 >> 1;                   // k-half within step
        a_off[mi] = row * 128 + ((c ^ (row & 7)) * 16);
    }
#pragma unroll
    for (int nj = 0; nj < 4; nj++) {
        int n = warpN * 64 + nj * 16 + (j8 >> 1) * 8 + rw;
        int c = j8 & 1;
        b_off[nj] = n * 128 + ((c ^ (n & 7)) * 16);
    }
    const uint32_t smem_base = (uint32_t)__cvta_generic_to_shared(smem);
    const uint32_t b_region  = smem_base + STAGES * A_STAGE_BYTES;

    // Warp tile 64x64: 4 M-frags x 8 N-frags
    float acc[4][8][4];
#pragma unroll
    for (int mi = 0; mi < 4; mi++)
#pragma unroll
        for (int ni = 0; ni < 8; ni++)
#pragma unroll
            for (int k = 0; k < 4; k++) acc[mi][ni][k] = 0.f;

    // Prologue: stages 0,1 (one committed group each)
    load_stage(Ag, Bg, As + 0 * A_STAGE_HALVES, Bs + 0 * B_STAGE_HALVES, 0, lr, lc);
    cp_commit();
    load_stage(Ag, Bg, As + 1 * A_STAGE_HALVES, Bs + 1 * B_STAGE_HALVES, 1, lr, lc);
    cp_commit();

    for (int kt = 0; kt < KT; kt++) {
        // Commit accounting: groups exist only for real loads. At iter kt the
        // pending set is {g_kt, g_{kt+1}} (or {g_{KT-1}} at the last iter).
        if (kt < KT - 1) cp_wait1(); else cp_wait0();
        __syncthreads();       // stage (kt+2)%3 fully consumed by all warps

        const uint32_t a_base = smem_base + (kt % STAGES) * A_STAGE_BYTES;
        const uint32_t b_base = b_region  + (kt % STAGES) * B_STAGE_BYTES;

        // Step-0 fragments first so MMAs restart ASAP after the barrier.
        uint32_t af[2][4][4];
        uint32_t bf[2][8][2];
#pragma unroll
        for (int mi = 0; mi < 4; mi++)
            ldsm_x4(af[0][mi], a_base + a_off[mi]);
#pragma unroll
        for (int nj = 0; nj < 4; nj++) {
            uint32_t r[4];
            ldsm_x4(r, b_base + b_off[nj]);
            bf[0][2 * nj][0]     = r[0];
            bf[0][2 * nj][1]     = r[1];
            bf[0][2 * nj + 1][0] = r[2];
            bf[0][2 * nj + 1][1] = r[3];
        }

        // Then the global->smem prefetch for stage kt+2.
        if (kt + 2 < KT) {
            int s = (kt + 2) % STAGES;
            load_stage(Ag, Bg, As + s * A_STAGE_HALVES, Bs + s * B_STAGE_HALVES,
                       kt + 2, lr, lc);
            cp_commit();
        }

#pragma unroll
        for (int s = 0; s < 4; s++) {        // four k16 steps per stage
            const int cur = s & 1;
            const int nxt = cur ^ 1;
            if (s < 3) {
                const uint32_t sx = (uint32_t)(s + 1) * 32;
#pragma unroll
                for (int mi = 0; mi < 4; mi++)
                    ldsm_x4(af[nxt][mi], a_base + (a_off[mi] ^ sx));
#pragma unroll
                for (int nj = 0; nj < 4; nj++) {
                    uint32_t r[4];
                    ldsm_x4(r, b_base + (b_off[nj] ^ sx));
                    bf[nxt][2 * nj][0]     = r[0];
                    bf[nxt][2 * nj][1]     = r[1];
                    bf[nxt][2 * nj + 1][0] = r[2];
                    bf[nxt][2 * nj + 1][1] = r[3];
                }
            }
#pragma unroll
            for (int mi = 0; mi < 4; mi++)
#pragma unroll
                for (int ni = 0; ni < 8; ni++)
                    mma_f16(acc[mi][ni], af[cur][mi], bf[cur][ni]);
        }
    }

    // Epilogue: fp32 stores
#pragma unroll
    for (int mi = 0; mi < 4; mi++) {
#pragma unroll
        for (int ni = 0; ni < 8; ni++) {
            int row = bm + warpM * 64 + mi * 16 + g;
            int col = bn + warpN * 64 + ni * 8 + t4 * 2;
            float2 v01 = make_float2(acc[mi][ni][0], acc[mi][ni][1]);
            float2 v23 = make_float2(acc[mi][ni][2], acc[mi][ni][3]);
            *reinterpret_cast<float2*>(C + (size_t)row * OUT + col)       = v01;
            *reinterpret_cast<float2*>(C + (size_t)(row + 8) * OUT + col) = v23;
        }
    }
}

// ---------------------------------------------------------------------------
// Harness entry
// ---------------------------------------------------------------------------
extern "C" void kernel_launch(void* const* d_in, const int* in_sizes, int n_in,
                              void* d_out, int out_size) {
    const float4* x4   = (const float4*)d_in[0];  // [8192,1024] fp32
    const float4* coef = (const float4*)d_in[1];  // [1024,1024,8] fp32
    const float*  w    = (const float*)d_in[2];   // [1024,1024] fp32
    float* out = (float*)d_out;                   // [8192,1024] fp32
    (void)in_sizes; (void)n_in; (void)out_size;

    // Prep: 1M x-vector items + 512K w_eff pair items
    const int NXH = BATCH * IN / 8;               // 1M
    const int NPREP = NXH + OUT * IN / 2;         // 1.5M
    prep_kernel<<<(NPREP + 255) / 256, 256>>>(x4, coef, w);

    // fp16 GEMM, 96 KB smem, occ 2
    static const int smem_bytes = STAGES * (A_STAGE_BYTES + B_STAGE_BYTES); // 98304
    cudaFuncSetAttribute(gemm_f16, cudaFuncAttributeMaxDynamicSharedMemorySize, smem_bytes);

    const __half* xr_dev;
    cudaGetSymbolAddress((void**)&xr_dev, g_xrh);
    dim3 grid(OUT / BN, BATCH / BM);  // (8, 64) = 512 CTAs
    gemm_f16<<<grid, THREADS, smem_bytes>>>(xr_dev, out);
}

// round 15
// speedup vs baseline: 1.8798x; 1.1400x over previous
#include <cuda_runtime.h>
#include <cuda_fp16.h>
#include <cstdint>

// Problem dims
#define BATCH 8192
#define IN    1024
#define OUT   1024

// GEMM tiling: block 64x128, 4 warps (2M x 2N), warp tile 32x64, fp16,
// 2-stage smem ring, occ 4.
#define BM 64
#define BN 128
#define BKH 64            // K-halves per stage (= 128 bytes per row)
#define KT (IN / BKH)     // 16 k-iterations
#define STAGES 2
#define THREADS 128

#define A_STAGE_HALVES (BM * BKH)           // 4096 halves = 8 KB
#define B_STAGE_HALVES (BN * BKH)           // 8192 halves = 16 KB
#define A_STAGE_BYTES (A_STAGE_HALVES * 2)
#define B_STAGE_BYTES (B_STAGE_HALVES * 2)

// Scratch: fp16-rounded operands, K-contiguous
__device__ __half g_weffh[OUT * IN];   // [O, I]
__device__ __half g_xrh[BATCH * IN];   // [B, I]

// ---------------------------------------------------------------------------
// Helpers
// ---------------------------------------------------------------------------
__device__ __forceinline__ uint32_t h2_bits(__half2 h) {
    return *reinterpret_cast<uint32_t*>(&h);
}
__device__ __forceinline__ void cp_async16(void* s, const void* g) {
    uint32_t sa = (uint32_t)__cvta_generic_to_shared(s);
    asm volatile("cp.async.cg.shared.global [%0], [%1], 16;\n" :: "r"(sa), "l"(g));
}
__device__ __forceinline__ void cp_commit() {
    asm volatile("cp.async.commit_group;\n");
}
__device__ __forceinline__ void cp_wait1() {
    asm volatile("cp.async.wait_group 1;\n");
}
__device__ __forceinline__ void cp_wait0() {
    asm volatile("cp.async.wait_group 0;\n");
}
__device__ __forceinline__ void ldsm_x4(uint32_t* r, uint32_t saddr) {
    asm volatile("ldmatrix.sync.aligned.m8n8.x4.shared.b16 {%0,%1,%2,%3}, [%4];"
        : "=r"(r[0]), "=r"(r[1]), "=r"(r[2]), "=r"(r[3]) : "r"(saddr));
}
// fp16 MMA, fp32 accumulate: D[16x8] += A[16x16] * B[16x8]
__device__ __forceinline__ void mma_f16(float* c, const uint32_t* a, const uint32_t* b) {
    asm volatile(
        "mma.sync.aligned.m16n8k16.row.col.f32.f16.f16.f32 "
        "{%0,%1,%2,%3},{%4,%5,%6,%7},{%8,%9},{%0,%1,%2,%3};\n"
        : "+f"(c[0]), "+f"(c[1]), "+f"(c[2]), "+f"(c[3])
        : "r"(a[0]), "r"(a[1]), "r"(a[2]), "r"(a[3]), "r"(b[0]), "r"(b[1]));
}

// ---------------------------------------------------------------------------
// Kernel A (prep): round x -> g_xrh (fp16-rn), build+round w_eff -> g_weffh
// ---------------------------------------------------------------------------
__global__ void prep_kernel(const float4* __restrict__ x4,
                            const float4* __restrict__ coef,
                            const float* __restrict__ w) {
    const int NXH = BATCH * IN / 8;          // 1M: each handles 8 floats of x
    int idx = blockIdx.x * blockDim.x + threadIdx.x;
    if (idx < NXH) {
        float4 v0 = x4[2 * idx];
        float4 v1 = x4[2 * idx + 1];
        uint4 out;
        out.x = h2_bits(__floats2half2_rn(v0.x, v0.y));
        out.y = h2_bits(__floats2half2_rn(v0.z, v0.w));
        out.z = h2_bits(__floats2half2_rn(v1.x, v1.y));
        out.w = h2_bits(__floats2half2_rn(v1.z, v1.w));
        reinterpret_cast<uint4*>(g_xrh)[idx] = out;
    } else {
        int i = (idx - NXH) * 2;             // 2 w_eff elements per thread
        float r0, r1;
        {
            float4 c0 = coef[2 * i];
            float4 c1 = coef[2 * i + 1];
            float s = ((c0.x + c0.y) + (c0.z + c0.w)) + ((c1.x + c1.y) + (c1.z + c1.w));
            r0 = s * w[i];
        }
        {
            float4 c0 = coef[2 * (i + 1)];
            float4 c1 = coef[2 * (i + 1) + 1];
            float s = ((c0.x + c0.y) + (c0.z + c0.w)) + ((c1.x + c1.y) + (c1.z + c1.w));
            r1 = s * w[i + 1];
        }
        reinterpret_cast<uint32_t*>(g_weffh)[i / 2] = h2_bits(__floats2half2_rn(r0, r1));
    }
}

// ---------------------------------------------------------------------------
// Kernel B: C[8192,1024] = Xh @ Weffh^T  (TN, fp16 mma.sync + ldmatrix,
//           64x128 tiles, 2-stage ring, occ 4)
// ---------------------------------------------------------------------------
// SMEM rows: 128 bytes (64 halves), 8 x 16B groups, swizzle group^=(row&7).
__device__ __forceinline__ void load_stage(const __half* __restrict__ Ag,
                                           const __half* __restrict__ Bg,
                                           __half* as, __half* bs,
                                           int kt, int lr, int lc) {
    int kofs = kt * BKH + lc * 8;            // half index within row
#pragma unroll
    for (int j = 0; j < 4; j++) {            // A: 64 rows / 16 per pass
        int r = lr + j * 16;
        int sw = (lc ^ (r & 7)) * 8;
        cp_async16(as + r * BKH + sw, Ag + (size_t)r * IN + kofs);
    }
#pragma unroll
    for (int j = 0; j < 8; j++) {            // B: 128 rows / 16 per pass
        int r = lr + j * 16;
        int sw = (lc ^ (r & 7)) * 8;
        cp_async16(bs + r * BKH + sw, Bg + (size_t)r * IN + kofs);
    }
}

__global__ void __launch_bounds__(THREADS, 4)
gemm_f16(const __half* __restrict__ A, float* __restrict__ C) {
    extern __shared__ __half smem[];
    __half* As = smem;                            // STAGES * A_STAGE_HALVES
    __half* Bs = smem + STAGES * A_STAGE_HALVES;  // STAGES * B_STAGE_HALVES

    const int tid    = threadIdx.x;
    const int warpId = tid >> 5;              // 0..3
    const int lane   = tid & 31;
    const int g      = lane >> 2;   // 0..7
    const int t4     = lane & 3;    // 0..3
    const int warpM  = warpId & 1;  // 2 warps in M (32 rows each)
    const int warpN  = warpId >> 1; // 2 warps in N (64 cols each)

    const int bm = blockIdx.y * BM;
    const int bn = blockIdx.x * BN;

    const int lr = tid >> 3;   // 0..15
    const int lc = tid & 7;    // 0..7

    const __half* Ag = A + (size_t)bm * IN;
    const __half* Bg = g_weffh + (size_t)bn * IN;

    // ldmatrix per-lane byte offsets (relative to stage A / stage B base).
    const int j8 = lane >> 3;   // which 8x8 matrix of the x4
    const int rw = lane & 7;    // row within it
    uint32_t a_off[2], b_off[4];
#pragma unroll
    for (int mi = 0; mi < 2; mi++) {
        int row = warpM * 32 + mi * 16 + (j8 & 1) * 8 + rw;
        int c   = j8 >> 1;                   // k-half within step
        a_off[mi] = row * 128 + ((c ^ (row & 7)) * 16);
    }
#pragma unroll
    for (int nj = 0; nj < 4; nj++) {
        int n = warpN * 64 + nj * 16 + (j8 >> 1) * 8 + rw;
        int c = j8 & 1;
        b_off[nj] = n * 128 + ((c ^ (n & 7)) * 16);
    }
    const uint32_t smem_base = (uint32_t)__cvta_generic_to_shared(smem);
    const uint32_t b_region  = smem_base + STAGES * A_STAGE_BYTES;

    // Warp tile 32x64: 2 M-frags x 8 N-frags
    float acc[2][8][4];
#pragma unroll
    for (int mi = 0; mi < 2; mi++)
#pragma unroll
        for (int ni = 0; ni < 8; ni++)
#pragma unroll
            for (int k = 0; k < 4; k++) acc[mi][ni][k] = 0.f;

    // Prologue: stage 0
    load_stage(Ag, Bg, As, Bs, 0, lr, lc);
    cp_commit();

    for (int kt = 0; kt < KT; kt++) {
        // Prefetch stage kt+1 into the other buffer (safe: that buffer was
        // consumed in iter kt-1 and released by the trailing barrier).
        if (kt + 1 < KT) {
            int s = (kt + 1) & 1;
            load_stage(Ag, Bg, As + s * A_STAGE_HALVES, Bs + s * B_STAGE_HALVES,
                       kt + 1, lr, lc);
            cp_commit();
            cp_wait1();        // stage kt's group done; kt+1 still in flight
        } else {
            cp_wait0();        // last stage
        }
        __syncthreads();       // make stage kt's data visible to all warps

        const uint32_t a_base = smem_base + (kt & 1) * A_STAGE_BYTES;
        const uint32_t b_base = b_region  + (kt & 1) * B_STAGE_BYTES;

#pragma unroll
        for (int s = 0; s < 4; s++) {        // four k16 steps per stage
            const uint32_t sx = (uint32_t)s * 32;
            uint32_t af[2][4];
            uint32_t bf[8][2];
#pragma unroll
            for (int mi = 0; mi < 2; mi++)
                ldsm_x4(af[mi], a_base + (a_off[mi] ^ sx));
#pragma unroll
            for (int nj = 0; nj < 4; nj++) {
                uint32_t r[4];
                ldsm_x4(r, b_base + (b_off[nj] ^ sx));
                bf[2 * nj][0]     = r[0];
                bf[2 * nj][1]     = r[1];
                bf[2 * nj + 1][0] = r[2];
                bf[2 * nj + 1][1] = r[3];
            }
#pragma unroll
            for (int mi = 0; mi < 2; mi++)
#pragma unroll
                for (int ni = 0; ni < 8; ni++)
                    mma_f16(acc[mi][ni], af[mi], bf[ni]);
        }

        __syncthreads();       // all warps done with stage kt before iter kt+1
                               // overwrites this buffer with stage kt+2
    }

    // Epilogue: fp32 stores
#pragma unroll
    for (int mi = 0; mi < 2; mi++) {
#pragma unroll
        for (int ni = 0; ni < 8; ni++) {
            int row = bm + warpM * 32 + mi * 16 + g;
            int col = bn + warpN * 64 + ni * 8 + t4 * 2;
            float2 v01 = make_float2(acc[mi][ni][0], acc[mi][ni][1]);
            float2 v23 = make_float2(acc[mi][ni][2], acc[mi][ni][3]);
            *reinterpret_cast<float2*>(C + (size_t)row * OUT + col)       = v01;
            *reinterpret_cast<float2*>(C + (size_t)(row + 8) * OUT + col) = v23;
        }
    }
}

// ---------------------------------------------------------------------------
// Harness entry
// ---------------------------------------------------------------------------
extern "C" void kernel_launch(void* const* d_in, const int* in_sizes, int n_in,
                              void* d_out, int out_size) {
    const float4* x4   = (const float4*)d_in[0];  // [8192,1024] fp32
    const float4* coef = (const float4*)d_in[1];  // [1024,1024,8] fp32
    const float*  w    = (const float*)d_in[2];   // [1024,1024] fp32
    float* out = (float*)d_out;                   // [8192,1024] fp32
    (void)in_sizes; (void)n_in; (void)out_size;

    // Prep: 1M x-vector items + 512K w_eff pair items
    const int NXH = BATCH * IN / 8;               // 1M
    const int NPREP = NXH + OUT * IN / 2;         // 1.5M
    prep_kernel<<<(NPREP + 255) / 256, 256>>>(x4, coef, w);

    // fp16 GEMM, 48 KB smem, occ 4
    static const int smem_bytes = STAGES * (A_STAGE_BYTES + B_STAGE_BYTES); // 49152
    cudaFuncSetAttribute(gemm_f16, cudaFuncAttributeMaxDynamicSharedMemorySize, smem_bytes);

    const __half* xr_dev;
    cudaGetSymbolAddress((void**)&xr_dev, g_xrh);
    dim3 grid(OUT / BN, BATCH / BM);  // (8, 128) = 1024 CTAs
    gemm_f16<<<grid, THREADS, smem_bytes>>>(xr_dev, out);
}